// round 12
// baseline (speedup 1.0000x reference)
#include <cuda_runtime.h>
#include <math.h>

#define BS 1024
#define SL 512
#define TT 64
#define RD 8     // e smem ring depth (steps); slot = s & 7

// Per-batch partials (static device globals: no allocation).
__device__ float g_score[BS];
__device__ float g_logZ[BS];
__device__ int   g_count[BS];

// ---- packed f32x2 helpers (PTX-only; ptxas won't auto-fuse) ----------------
__device__ __forceinline__ unsigned long long ffma2(unsigned long long a,
                                                    unsigned long long b,
                                                    unsigned long long c) {
    unsigned long long d;
    asm("fma.rn.f32x2 %0, %1, %2, %3;" : "=l"(d) : "l"(a), "l"(b), "l"(c));
    return d;
}
__device__ __forceinline__ unsigned long long addf2(unsigned long long a,
                                                    unsigned long long b) {
    unsigned long long d;
    asm("add.rn.f32x2 %0, %1, %2;" : "=l"(d) : "l"(a), "l"(b));
    return d;
}
__device__ __forceinline__ unsigned long long pack2(float x, float y) {
    unsigned long long r;
    asm("mov.b64 %0, {%1, %2};" : "=l"(r) : "f"(x), "f"(y));
    return r;
}
__device__ __forceinline__ void unpack2(unsigned long long v, float& lo, float& hi) {
    asm("mov.b64 {%0, %1}, %2;" : "=f"(lo), "=f"(hi) : "l"(v));
}
__device__ __forceinline__ float rcp_approx(float x) {
    float r;
    asm("rcp.approx.f32 %0, %1;" : "=f"(r) : "f"(x));
    return r;
}
// ---- cp.async -------------------------------------------------------------
__device__ __forceinline__ unsigned smem_u32(const void* p) {
    unsigned a;
    asm("{ .reg .u64 t; cvta.to.shared.u64 t, %1; cvt.u32.u64 %0, t; }"
        : "=r"(a) : "l"(p));
    return a;
}
__device__ __forceinline__ void cp_async4(unsigned dst, const void* src) {
    asm volatile("cp.async.ca.shared.global [%0], [%1], 4;"
                 :: "r"(dst), "l"(src) : "memory");
}
__device__ __forceinline__ void cp_commit() {
    asm volatile("cp.async.commit_group;" ::: "memory");
}
__device__ __forceinline__ void cp_wait6() {
    asm volatile("cp.async.wait_group 6;" ::: "memory");
}
// ---- named barrier: sync one 64-thread pair (2 warps) ----------------------
__device__ __forceinline__ void barp(int id) {
    asm volatile("bar.sync %0, 64;" :: "r"(id) : "memory");
}

// ---------------------------------------------------------------------------
// Score kernel: per-batch tag-path score + mask count.
// ---------------------------------------------------------------------------
__global__ void crf_score_kernel(const float* __restrict__ e,
                                 const int* __restrict__ tags,
                                 const unsigned char* __restrict__ mask,
                                 const float* __restrict__ st,
                                 const float* __restrict__ et,
                                 const float* __restrict__ t)
{
    const int b = blockIdx.x;
    const int tid = threadIdx.x;               // 128 threads
    const int* tg = tags + b * SL;
    const unsigned char* mk = mask + b * SL;
    const float* eb = e + (size_t)b * SL * TT;

    float s_local = 0.f;
    int c_local = 0;
    for (int s = tid; s < SL; s += 128) {
        int tag = tg[s];
        int m = mk[s] ? 1 : 0;
        if (s == 0) {
            s_local += st[tag] + eb[tag];
        } else if (m) {
            int tp = tg[s - 1];
            s_local += t[tp * TT + tag] + eb[(size_t)s * TT + tag];
        }
        c_local += m;
    }

    __shared__ float ssum[128];
    __shared__ int   scnt[128];
    ssum[tid] = s_local;
    scnt[tid] = c_local;
    __syncthreads();
    for (int off = 64; off > 0; off >>= 1) {
        if (tid < off) {
            ssum[tid] += ssum[tid + off];
            scnt[tid] += scnt[tid + off];
        }
        __syncthreads();
    }
    if (tid == 0) {
        float sc = ssum[0];
        int cnt = scnt[0];
        if (cnt > 0) sc += et[tg[cnt - 1]];
        g_score[b] = sc;
        g_count[b] = cnt;
    }
}

// ---------------------------------------------------------------------------
// Forward kernel: 128-thread blocks = TWO independent batch-pairs.
//   pair = tid>>6 handles batch 2*blockIdx + pair; thread owns ONE state j.
//   Pair 0 = warps 0,1 (SMSP 0,1); pair 1 = warps 2,3 (SMSP 2,3) -> all 4
//   SMSPs active (R8's 64-thread blocks pinned everything to SMSP 0/1:
//   issue was ~97% on the active half). Pairs sync via their own named
//   barrier (bar.sync 1+pair, 64) -> no cross-pair coupling (R5's mistake).
// Per thread-step: 16 LDS.128 + 32 FFMA2 (96 regs -> one wave, 2048 warps).
// e staged global->smem via cp.async ring; mask preloaded to smem.
// Linear-domain alpha, renormalized by a_prev[0] each step:
//   a_new[j] = (sum_i a[i]*P[i][j]) * exp(e[s][j]) * rcp(a0);  logb += log2(a0)
// ---------------------------------------------------------------------------
__global__ void __launch_bounds__(128)
crf_forward_kernel(const float* __restrict__ e,
                   const unsigned char* __restrict__ mask,
                   const float* __restrict__ st,
                   const float* __restrict__ et,
                   const float* __restrict__ t)
{
    const int tid = threadIdx.x;
    const int pair = tid >> 6;                 // 0,1: batch within block
    const int j = tid & (TT - 1);              // state index
    const int b = blockIdx.x * 2 + pair;
    const int barid = 1 + pair;

    __shared__ __align__(16) float a_sm[2][2][TT];     // [pair][buf][state]
    __shared__ __align__(16) float e_sm[2][RD][TT];
    __shared__ __align__(8)  unsigned char m_sm[2][SL];
    __shared__ float wred[2][2];

    // Packed P column j: Pp[q] = { exp(t[2q][j]), exp(t[2q+1][j]) }  (64 regs)
    unsigned long long Pp[TT / 2];
#pragma unroll
    for (int q = 0; q < TT / 2; q++) {
        float p0 = __expf(t[(2 * q + 0) * TT + j]);
        float p1 = __expf(t[(2 * q + 1) * TT + j]);
        Pp[q] = pack2(p0, p1);
    }

    const float* eb = e + (size_t)b * SL * TT;
    const unsigned char* mk = mask + b * SL;

    // Preload full mask row (64 threads x 8B = 512B).
    ((unsigned long long*)m_sm[pair])[j] = ((const unsigned long long*)mk)[j];

    // Prologue: e slices 1..8 in flight, one commit group each.
    const unsigned ej = smem_u32(&e_sm[pair][0][0]) + (j << 2);
#pragma unroll
    for (int i = 1; i <= RD; i++) {
        cp_async4(ej + ((i & (RD - 1)) * TT << 2), &eb[(size_t)i * TT + j]);
        cp_commit();
    }

    float a = __expf(st[j] + eb[j]);           // linear alpha, step 0
    float logb = 0.f;

    int par = 0;
    a_sm[pair][0][j] = a;
    barp(barid);
    cp_wait6();                                // slices 1,2 ready
    float E = __expf(e_sm[pair][1][j]);
    int mcur = m_sm[pair][1];

#pragma unroll 2
    for (int s = 1; s < SL; ++s) {
        // Keep the pipe full: slices <= s+1 complete; issue slice s+RD.
        cp_wait6();
        if (s + RD < SL)
            cp_async4(ej + ((s & (RD - 1)) * TT << 2),
                      &eb[(size_t)(s + RD) * TT + j]);
        cp_commit();

        // Renorm anchor (off critical path; overlaps the dot).
        float a0 = a_sm[pair][par][0];
        float r  = rcp_approx(a0);
        float lg = __log2f(a0);

        const ulonglong2* av = (const ulonglong2*)(a_sm[pair][par]);
        unsigned long long acc0 = 0ull, acc1 = 0ull, acc2 = 0ull, acc3 = 0ull;
#pragma unroll
        for (int q2 = 0; q2 < TT / 4; q2++) {
            ulonglong2 v = av[q2];             // LDS.128 broadcast
            if (q2 & 1) {
                acc2 = ffma2(v.x, Pp[2 * q2 + 0], acc2);
                acc3 = ffma2(v.y, Pp[2 * q2 + 1], acc3);
            } else {
                acc0 = ffma2(v.x, Pp[2 * q2 + 0], acc0);
                acc1 = ffma2(v.y, Pp[2 * q2 + 1], acc1);
            }
        }
        unsigned long long sp = addf2(addf2(acc0, acc2), addf2(acc1, acc3));
        float slo, shi;
        unpack2(sp, slo, shi);
        float sum = slo + shi;

        if (mcur) {
            a = sum * (E * r);
            logb += lg;
        }

        // Next-step operands (slice s+1 complete by the wait above).
        int sn = (s + 1 < SL) ? (s + 1) : (SL - 1);
        E = __expf(e_sm[pair][sn & (RD - 1)][j]);
        mcur = m_sm[pair][sn];

        par ^= 1;
        a_sm[pair][par][j] = a;
        barp(barid);                           // pair-private barrier
    }

    // logZ = ln2*(logb + log2( sum_j a[j]*exp(et[j]) ))
    float f = a * __expf(et[j]);
    const int lane = tid & 31;
    const int wip = (tid >> 5) & 1;            // warp within pair
#pragma unroll
    for (int off = 16; off > 0; off >>= 1)
        f += __shfl_xor_sync(0xffffffffu, f, off);
    if (lane == 0) wred[pair][wip] = f;
    barp(barid);
    if (j == 0) {
        float total = wred[pair][0] + wred[pair][1];
        g_logZ[b] = 0.69314718055994531f * (logb + __log2f(total));
    }
}

// ---------------------------------------------------------------------------
// Deterministic final reduction: out = sum_b(score_b - logZ_b) / sum(mask)
// ---------------------------------------------------------------------------
__global__ void crf_finalize_kernel(float* __restrict__ out)
{
    const int tid = threadIdx.x;               // 256 threads
    float num = 0.f, tot = 0.f;
    for (int b = tid; b < BS; b += 256) {
        num += g_score[b] - g_logZ[b];
        tot += (float)g_count[b];
    }
    __shared__ float sn[256], stt[256];
    sn[tid] = num;
    stt[tid] = tot;
    __syncthreads();
    for (int off = 128; off > 0; off >>= 1) {
        if (tid < off) {
            sn[tid]  += sn[tid + off];
            stt[tid] += stt[tid + off];
        }
        __syncthreads();
    }
    if (tid == 0) out[0] = sn[0] / stt[0];
}

// ---------------------------------------------------------------------------
// Inputs (metadata order): e(f32), tags(i32), mask(bool->u8), st(f32),
// et(f32), t(f32). Output: single f32 scalar.
// ---------------------------------------------------------------------------
extern "C" void kernel_launch(void* const* d_in, const int* in_sizes, int n_in,
                              void* d_out, int out_size)
{
    const float*         e    = (const float*)d_in[0];
    const int*           tags = (const int*)d_in[1];
    const unsigned char* mask = (const unsigned char*)d_in[2];
    const float*         st   = (const float*)d_in[3];
    const float*         et   = (const float*)d_in[4];
    const float*         t    = (const float*)d_in[5];
    float* out = (float*)d_out;

    crf_forward_kernel<<<BS / 2, 128>>>(e, mask, st, et, t);
    crf_score_kernel<<<BS, 128>>>(e, tags, mask, st, et, t);
    crf_finalize_kernel<<<1, 256>>>(out);
}

// round 14
// speedup vs baseline: 1.3125x; 1.3125x over previous
#include <cuda_runtime.h>
#include <math.h>

#define BS 1024
#define SL 512
#define TT 64
#define RD 8     // e smem ring depth (steps); slot = s & 7
#define WPB 8    // warps per block = batches per block (grid 128 = 1 block/SM)

// Per-batch partials (static device globals: no allocation).
__device__ float g_score[BS];
__device__ float g_logZ[BS];
__device__ int   g_count[BS];

// ---- packed f32x2 helpers (PTX-only; ptxas won't auto-fuse) ----------------
__device__ __forceinline__ unsigned long long ffma2(unsigned long long a,
                                                    unsigned long long b,
                                                    unsigned long long c) {
    unsigned long long d;
    asm("fma.rn.f32x2 %0, %1, %2, %3;" : "=l"(d) : "l"(a), "l"(b), "l"(c));
    return d;
}
__device__ __forceinline__ unsigned long long addf2(unsigned long long a,
                                                    unsigned long long b) {
    unsigned long long d;
    asm("add.rn.f32x2 %0, %1, %2;" : "=l"(d) : "l"(a), "l"(b));
    return d;
}
__device__ __forceinline__ unsigned long long pack2(float x, float y) {
    unsigned long long r;
    asm("mov.b64 %0, {%1, %2};" : "=l"(r) : "f"(x), "f"(y));
    return r;
}
__device__ __forceinline__ void unpack2(unsigned long long v, float& lo, float& hi) {
    asm("mov.b64 {%0, %1}, %2;" : "=f"(lo), "=f"(hi) : "l"(v));
}
__device__ __forceinline__ float rcp_approx(float x) {
    float r;
    asm("rcp.approx.f32 %0, %1;" : "=f"(r) : "f"(x));
    return r;
}
// ---- cp.async -------------------------------------------------------------
__device__ __forceinline__ unsigned smem_u32(const void* p) {
    unsigned a;
    asm("{ .reg .u64 t; cvta.to.shared.u64 t, %1; cvt.u32.u64 %0, t; }"
        : "=r"(a) : "l"(p));
    return a;
}
__device__ __forceinline__ void cp_async8(unsigned dst, const void* src) {
    asm volatile("cp.async.ca.shared.global [%0], [%1], 8;"
                 :: "r"(dst), "l"(src) : "memory");
}
__device__ __forceinline__ void cp_commit() {
    asm volatile("cp.async.commit_group;" ::: "memory");
}
__device__ __forceinline__ void cp_wait6() {
    asm volatile("cp.async.wait_group 6;" ::: "memory");
}

// ---------------------------------------------------------------------------
// Score kernel: per-batch tag-path score + mask count.
// ---------------------------------------------------------------------------
__global__ void crf_score_kernel(const float* __restrict__ e,
                                 const int* __restrict__ tags,
                                 const unsigned char* __restrict__ mask,
                                 const float* __restrict__ st,
                                 const float* __restrict__ et,
                                 const float* __restrict__ t)
{
    const int b = blockIdx.x;
    const int tid = threadIdx.x;               // 128 threads
    const int* tg = tags + b * SL;
    const unsigned char* mk = mask + b * SL;
    const float* eb = e + (size_t)b * SL * TT;

    float s_local = 0.f;
    int c_local = 0;
    for (int s = tid; s < SL; s += 128) {
        int tag = tg[s];
        int m = mk[s] ? 1 : 0;
        if (s == 0) {
            s_local += st[tag] + eb[tag];
        } else if (m) {
            int tp = tg[s - 1];
            s_local += t[tp * TT + tag] + eb[(size_t)s * TT + tag];
        }
        c_local += m;
    }

    __shared__ float ssum[128];
    __shared__ int   scnt[128];
    ssum[tid] = s_local;
    scnt[tid] = c_local;
    __syncthreads();
    for (int off = 64; off > 0; off >>= 1) {
        if (tid < off) {
            ssum[tid] += ssum[tid + off];
            scnt[tid] += scnt[tid + off];
        }
        __syncthreads();
    }
    if (tid == 0) {
        float sc = ssum[0];
        int cnt = scnt[0];
        if (cnt > 0) sc += et[tg[cnt - 1]];
        g_score[b] = sc;
        g_count[b] = cnt;
    }
}

// ---------------------------------------------------------------------------
// Forward kernel: 8 INDEPENDENT warps per 256-thread block, one batch per
// warp, 2 states per thread (lane l owns states 2l, 2l+1). Grid = 128 blocks
// -> EXACTLY one block per SM (R10's grid=256 left 40 SMs with a single
// block whose lone warp/SMSP ran the full ~590cyc serial chain and set the
// kernel duration). Here every active SM has 2 warps/SMSP, balanced.
// Per warp-step: STS.64 -> syncwarp -> 16 LDS.128 -> 64 fma.f32x2.
// Renorm every 4 steps (bounded growth ~1e16 < fp32 max; R11-proven).
// Steps run 1..512 in 128 chunks of 4; step 512 is a masked dummy.
// e staged via cp.async smem ring; mask preloaded to smem per warp.
// ---------------------------------------------------------------------------
__global__ void __launch_bounds__(32 * WPB)
crf_forward_kernel(const float* __restrict__ e,
                   const unsigned char* __restrict__ mask,
                   const float* __restrict__ st,
                   const float* __restrict__ et,
                   const float* __restrict__ t)
{
    const int tid = threadIdx.x;
    const int w = tid >> 5;                    // warp = batch within block
    const int l = tid & 31;                    // lane
    const int b = blockIdx.x * WPB + w;
    const int j0 = 2 * l;                      // owned states j0, j0+1

    __shared__ __align__(16) float a_sm[WPB][2][TT];
    __shared__ __align__(16) float e_sm[WPB][RD][TT];
    __shared__ __align__(16) unsigned char m_sm[WPB][SL];

    // Packed P columns: P0[q]=(exp t[2q][j0], exp t[2q+1][j0]), P1 likewise j0+1.
    unsigned long long P0[TT / 2], P1[TT / 2];
#pragma unroll
    for (int q = 0; q < TT / 2; q++) {
        float2 ta = *(const float2*)&t[(2 * q + 0) * TT + j0];
        float2 tb = *(const float2*)&t[(2 * q + 1) * TT + j0];
        P0[q] = pack2(__expf(ta.x), __expf(tb.x));
        P1[q] = pack2(__expf(ta.y), __expf(tb.y));
    }

    const float* eb = e + (size_t)b * SL * TT;
    const unsigned char* mk = mask + b * SL;

    // Preload mask row to smem (32 lanes x 16B = 512B).
    *(uint4*)&m_sm[w][l * 16] = *(const uint4*)&mk[l * 16];

    // Prologue: e slices 1..8 in flight, one commit group each (8B/lane).
    const unsigned e_base = smem_u32(&e_sm[w][0][0]);
#pragma unroll
    for (int i = 1; i <= RD; i++) {
        cp_async8(e_base + (((i & (RD - 1)) * TT + j0) << 2),
                  &eb[(size_t)i * TT + j0]);
        cp_commit();
    }

    // Step 0 init.
    float2 e0 = *(const float2*)&eb[j0];
    float ax = __expf(st[j0] + e0.x);
    float ay = __expf(st[j0 + 1] + e0.y);
    float logb = 0.f;

    int par = 0;
    *(float2*)&a_sm[w][0][j0] = make_float2(ax, ay);
    __syncwarp();
    cp_wait6();                                // slices 1,2 ready
    float2 ev1 = *(const float2*)&e_sm[w][1][j0];
    float Ex = __expf(ev1.x);
    float Ey = __expf(ev1.y);
    int mcur = m_sm[w][1];

    // 128 chunks of 4 steps: s = 1..512 (s=512 is a masked dummy).
    for (int s0 = 1; s0 <= 509; s0 += 4) {
#pragma unroll
        for (int k = 0; k < 4; k++) {
            const int s = s0 + k;

            // Keep the pipe full: slices <= s+1 complete; issue slice s+RD.
            cp_wait6();
            if (s + RD < SL)
                cp_async8(e_base + (((s & (RD - 1)) * TT + j0) << 2),
                          &eb[(size_t)(s + RD) * TT + j0]);
            cp_commit();

            const ulonglong2* av = (const ulonglong2*)(a_sm[w][par]);
            unsigned long long c0a = 0ull, c0b = 0ull;
            unsigned long long c1a = 0ull, c1b = 0ull;
#pragma unroll
            for (int q2 = 0; q2 < TT / 4; q2++) {
                ulonglong2 v = av[q2];         // LDS.128 broadcast: 4 alphas
                c0a = ffma2(v.x, P0[2 * q2 + 0], c0a);
                c0b = ffma2(v.y, P0[2 * q2 + 1], c0b);
                c1a = ffma2(v.x, P1[2 * q2 + 0], c1a);
                c1b = ffma2(v.y, P1[2 * q2 + 1], c1b);
            }
            float s0lo, s0hi, s1lo, s1hi;
            unpack2(addf2(c0a, c0b), s0lo, s0hi);
            unpack2(addf2(c1a, c1b), s1lo, s1hi);
            float nx = (s0lo + s0hi) * Ex;
            float ny = (s1lo + s1hi) * Ey;
            if (mcur) { ax = nx; ay = ny; }

            if (k == 3) {                      // renorm every 4 steps
                float a0 = __shfl_sync(0xffffffffu, ax, 0);
                float r = rcp_approx(a0);
                ax *= r; ay *= r;
                logb += __log2f(a0);
            }

            // Next-step operands (slice s+1 complete; clamp past the end).
            int sn = (s + 1 < SL) ? (s + 1) : (SL - 1);
            float2 ev = *(const float2*)&e_sm[w][sn & (RD - 1)][j0];
            Ex = __expf(ev.x);
            Ey = __expf(ev.y);
            mcur = (s + 1 < SL) ? m_sm[w][s + 1] : 0;

            par ^= 1;
            *(float2*)&a_sm[w][par][j0] = make_float2(ax, ay);
            __syncwarp();                      // warp-private; no BAR
        }
    }

    // logZ = ln2*(logb + log2( sum_j a[j]*exp(et[j]) ))
    float2 etv = *(const float2*)&et[j0];
    float f = ax * __expf(etv.x) + ay * __expf(etv.y);
#pragma unroll
    for (int off = 16; off > 0; off >>= 1)
        f += __shfl_xor_sync(0xffffffffu, f, off);
    if (l == 0)
        g_logZ[b] = 0.69314718055994531f * (logb + __log2f(f));
}

// ---------------------------------------------------------------------------
// Deterministic final reduction: out = sum_b(score_b - logZ_b) / sum(mask)
// ---------------------------------------------------------------------------
__global__ void crf_finalize_kernel(float* __restrict__ out)
{
    const int tid = threadIdx.x;               // 256 threads
    float num = 0.f, tot = 0.f;
    for (int b = tid; b < BS; b += 256) {
        num += g_score[b] - g_logZ[b];
        tot += (float)g_count[b];
    }
    __shared__ float sn[256], stt[256];
    sn[tid] = num;
    stt[tid] = tot;
    __syncthreads();
    for (int off = 128; off > 0; off >>= 1) {
        if (tid < off) {
            sn[tid]  += sn[tid + off];
            stt[tid] += stt[tid + off];
        }
        __syncthreads();
    }
    if (tid == 0) out[0] = sn[0] / stt[0];
}

// ---------------------------------------------------------------------------
// Inputs (metadata order): e(f32), tags(i32), mask(bool->u8), st(f32),
// et(f32), t(f32). Output: single f32 scalar.
// ---------------------------------------------------------------------------
extern "C" void kernel_launch(void* const* d_in, const int* in_sizes, int n_in,
                              void* d_out, int out_size)
{
    const float*         e    = (const float*)d_in[0];
    const int*           tags = (const int*)d_in[1];
    const unsigned char* mask = (const unsigned char*)d_in[2];
    const float*         st   = (const float*)d_in[3];
    const float*         et   = (const float*)d_in[4];
    const float*         t    = (const float*)d_in[5];
    float* out = (float*)d_out;

    crf_forward_kernel<<<BS / WPB, 32 * WPB>>>(e, mask, st, et, t);
    crf_score_kernel<<<BS, 128>>>(e, tags, mask, st, et, t);
    crf_finalize_kernel<<<1, 256>>>(out);
}